// round 1
// baseline (speedup 1.0000x reference)
#include <cuda_runtime.h>
#include <cstdint>

#define DIMC     1024
#define HEADS    16
#define HEAD_DIM 64
#define NTOK     49
#define BATCH    1024
#define MROWS    (BATCH * NTOK)   // 50176
#define SCALE    0.125f           // 64^-0.5

// ---------------- scratch (device globals: allocation-free) ----------------
__device__ float g_Q[(size_t)MROWS * DIMC];
__device__ float g_K[(size_t)MROWS * DIMC];
__device__ float g_V[(size_t)MROWS * DIMC];

// ---------------- helpers ----------------
__device__ __forceinline__ unsigned f2tf(float x) {
    unsigned r;
    asm("cvt.rna.tf32.f32 %0, %1;" : "=r"(r) : "f"(x));
    return r;
}

__device__ __forceinline__ void mma_tf32(float c[4],
                                         unsigned a0, unsigned a1, unsigned a2, unsigned a3,
                                         unsigned b0, unsigned b1) {
    asm volatile(
        "mma.sync.aligned.m16n8k8.row.col.f32.tf32.tf32.f32 "
        "{%0,%1,%2,%3}, {%4,%5,%6,%7}, {%8,%9}, {%0,%1,%2,%3};\n"
        : "+f"(c[0]), "+f"(c[1]), "+f"(c[2]), "+f"(c[3])
        : "r"(a0), "r"(a1), "r"(a2), "r"(a3), "r"(b0), "r"(b1));
}

__device__ __forceinline__ void cp_async16(uint32_t saddr, const void* g) {
    asm volatile("cp.async.cg.shared.global [%0], [%1], 16;\n" :: "r"(saddr), "l"(g) : "memory");
}
__device__ __forceinline__ void cp_commit() {
    asm volatile("cp.async.commit_group;\n" ::: "memory");
}
__device__ __forceinline__ void cp_wait0() {
    asm volatile("cp.async.wait_group 0;\n" ::: "memory");
}

// ---------------- TF32 GEMM: Y[M,1024] = X[M,1024] @ W[1024,1024]^T + bias ----------------
#define BM 128
#define BN 128
#define BK 16
#define PADK 20   // smem row stride in floats (conflict-free for frag reads)

__global__ __launch_bounds__(256) void gemm_tf32_kernel(
    const float* __restrict__ X_ext, const float* __restrict__ W,
    const float* __restrict__ bias, float* __restrict__ Y_ext,
    int xsel, int ysel)
{
    // selector avoids any host-side symbol-address lookup
    const float* X = (xsel == 0) ? X_ext : (const float*)g_Q;
    float* Y = Y_ext;
    if (ysel == 1) Y = g_Q; else if (ysel == 2) Y = g_K; else if (ysel == 3) Y = g_V;

    __shared__ __align__(16) float As[2][BM * PADK];
    __shared__ __align__(16) float Bs[2][BN * PADK];

    const int tid  = threadIdx.x;
    const int warp = tid >> 5;
    const int lane = tid & 31;
    const int wm   = warp >> 2;   // 0..1
    const int wn   = warp & 3;    // 0..3
    const int m0g  = blockIdx.y * BM;
    const int n0g  = blockIdx.x * BN;

    float acc[4][4][4];
#pragma unroll
    for (int mi = 0; mi < 4; ++mi)
#pragma unroll
        for (int ni = 0; ni < 4; ++ni)
#pragma unroll
            for (int r = 0; r < 4; ++r) acc[mi][ni][r] = 0.f;

    const uint32_t sA = (uint32_t)__cvta_generic_to_shared(&As[0][0]);
    const uint32_t sB = (uint32_t)__cvta_generic_to_shared(&Bs[0][0]);

    // tile load: 128x16 floats from each of X and W
    auto load_tile = [&](int buf, int kt) {
#pragma unroll
        for (int i = 0; i < 2; ++i) {
            int id  = tid + i * 256;          // 0..511
            int row = id >> 2;                // 0..127
            int c4  = (id & 3) << 2;          // 0,4,8,12
            uint32_t so = (uint32_t)((buf * BM * PADK + row * PADK + c4) * 4);
            cp_async16(sA + so, X + (size_t)(m0g + row) * DIMC + kt * BK + c4);
            cp_async16(sB + so, W + (size_t)(n0g + row) * DIMC + kt * BK + c4);
        }
        cp_commit();
    };

    load_tile(0, 0);

    const int KT = DIMC / BK;   // 64
    for (int kt = 0; kt < KT; ++kt) {
        cp_wait0();
        __syncthreads();
        int buf = kt & 1;
        if (kt + 1 < KT) load_tile(buf ^ 1, kt + 1);

        const float* Asb = &As[buf][0];
        const float* Bsb = &Bs[buf][0];
#pragma unroll
        for (int kk = 0; kk < BK; kk += 8) {
            unsigned af[4][4];
            unsigned bf[4][2];
#pragma unroll
            for (int mi = 0; mi < 4; ++mi) {
                int r = wm * 64 + mi * 16 + (lane >> 2);
                int c = kk + (lane & 3);
                af[mi][0] = f2tf(Asb[r * PADK + c]);
                af[mi][1] = f2tf(Asb[(r + 8) * PADK + c]);
                af[mi][2] = f2tf(Asb[r * PADK + c + 4]);
                af[mi][3] = f2tf(Asb[(r + 8) * PADK + c + 4]);
            }
#pragma unroll
            for (int ni = 0; ni < 4; ++ni) {
                int rn = wn * 32 + ni * 8 + (lane >> 2);
                int c  = kk + (lane & 3);
                bf[ni][0] = f2tf(Bsb[rn * PADK + c]);
                bf[ni][1] = f2tf(Bsb[rn * PADK + c + 4]);
            }
#pragma unroll
            for (int mi = 0; mi < 4; ++mi)
#pragma unroll
                for (int ni = 0; ni < 4; ++ni)
                    mma_tf32(acc[mi][ni], af[mi][0], af[mi][1], af[mi][2], af[mi][3],
                             bf[ni][0], bf[ni][1]);
        }
    }

    // epilogue: + bias, float2 stores
#pragma unroll
    for (int mi = 0; mi < 4; ++mi) {
        int r0 = m0g + wm * 64 + mi * 16 + (lane >> 2);
#pragma unroll
        for (int ni = 0; ni < 4; ++ni) {
            int cc = n0g + wn * 32 + ni * 8 + ((lane & 3) << 1);
            float bv0 = bias[cc], bv1 = bias[cc + 1];
            float2 v0 = make_float2(acc[mi][ni][0] + bv0, acc[mi][ni][1] + bv1);
            float2 v1 = make_float2(acc[mi][ni][2] + bv0, acc[mi][ni][3] + bv1);
            *(float2*)&Y[(size_t)r0 * DIMC + cc]       = v0;
            *(float2*)&Y[(size_t)(r0 + 8) * DIMC + cc] = v1;
        }
    }
}

// ---------------- fused windowed attention per (b,h) ----------------
// scores = (q k^T)*scale + bias[h]; softmax; out = p v  -> written into g_Q slice
__global__ __launch_bounds__(256) void attn_kernel(
    const float* __restrict__ bias_table, const int* __restrict__ rel_idx)
{
    __shared__ float sq[NTOK * 64];
    __shared__ float sv[NTOK * 64];
    __shared__ float sk[NTOK * 65];      // odd stride: conflict-free over j
    __shared__ float sp[NTOK * NTOK];    // bias, then probs (reused)

    const int b = blockIdx.x;
    const int h = blockIdx.y;
    const int tid  = threadIdx.x;
    const int warp = tid >> 5;
    const int lane = tid & 31;

    const size_t base = (size_t)(b * NTOK) * DIMC + h * HEAD_DIM;

    // load q,k,v tiles (float4)
    for (int t = tid; t < NTOK * 16; t += 256) {
        int row = t >> 4;
        int c4  = (t & 15) << 2;
        float4 qv = *(const float4*)&g_Q[base + (size_t)row * DIMC + c4];
        float4 kv = *(const float4*)&g_K[base + (size_t)row * DIMC + c4];
        float4 vv = *(const float4*)&g_V[base + (size_t)row * DIMC + c4];
        *(float4*)&sq[row * 64 + c4] = qv;
        *(float4*)&sv[row * 64 + c4] = vv;
        sk[row * 65 + c4 + 0] = kv.x;
        sk[row * 65 + c4 + 1] = kv.y;
        sk[row * 65 + c4 + 2] = kv.z;
        sk[row * 65 + c4 + 3] = kv.w;
    }
    // gather relative-position bias for this head
    for (int t = tid; t < NTOK * NTOK; t += 256)
        sp[t] = bias_table[rel_idx[t] * HEADS + h];
    __syncthreads();

    // scores + softmax: one warp per query row
    for (int i = warp; i < NTOK; i += 8) {
        const float* qi = &sq[i * 64];
        int j1 = lane;
        int j2 = lane + 32;
        int j2c = (j2 < NTOK) ? j2 : 0;
        const float* k1 = &sk[j1 * 65];
        const float* k2 = &sk[j2c * 65];
        float s1 = 0.f, s2 = 0.f;
#pragma unroll
        for (int d = 0; d < 64; ++d) {
            float qd = qi[d];
            s1 = fmaf(qd, k1[d], s1);
            s2 = fmaf(qd, k2[d], s2);
        }
        s1 = s1 * SCALE + sp[i * NTOK + j1];
        float s2v = (j2 < NTOK) ? (s2 * SCALE + sp[i * NTOK + j2]) : -1e30f;

        float m = fmaxf(s1, s2v);
#pragma unroll
        for (int off = 16; off > 0; off >>= 1)
            m = fmaxf(m, __shfl_xor_sync(0xFFFFFFFFu, m, off));
        float e1 = __expf(s1 - m);
        float e2 = (j2 < NTOK) ? __expf(s2v - m) : 0.f;
        float sum = e1 + e2;
#pragma unroll
        for (int off = 16; off > 0; off >>= 1)
            sum += __shfl_xor_sync(0xFFFFFFFFu, sum, off);
        float inv = 1.f / sum;
        sp[i * NTOK + j1] = e1 * inv;
        if (j2 < NTOK) sp[i * NTOK + j2] = e2 * inv;
    }
    __syncthreads();

    // out[i][d] = sum_j p[i][j] * v[j][d]; write back into g_Q slice
    for (int t = tid; t < NTOK * 64; t += 256) {
        int i = t >> 6;
        int d = t & 63;
        const float* pi = &sp[i * NTOK];
        float a = 0.f;
#pragma unroll
        for (int j = 0; j < NTOK; ++j)
            a = fmaf(pi[j], sv[j * 64 + d], a);
        g_Q[base + (size_t)i * DIMC + d] = a;
    }
}

// ---------------- launch ----------------
extern "C" void kernel_launch(void* const* d_in, const int* in_sizes, int n_in,
                              void* d_out, int out_size) {
    const float* landmark = (const float*)d_in[0];
    const float* image    = (const float*)d_in[1];
    const float* Wq = (const float*)d_in[2];
    const float* bq = (const float*)d_in[3];
    const float* Wk = (const float*)d_in[4];
    const float* bk = (const float*)d_in[5];
    const float* Wv = (const float*)d_in[6];
    const float* bv = (const float*)d_in[7];
    const float* Wo = (const float*)d_in[8];
    const float* bo = (const float*)d_in[9];
    const float* bt = (const float*)d_in[10];
    const int*   ri = (const int*)d_in[11];
    float* out = (float*)d_out;

    dim3 gg(DIMC / BN, MROWS / BM);   // (8, 392)

    // projections -> scratch
    gemm_tf32_kernel<<<gg, 256>>>(landmark, Wq, bq, nullptr, 0, 1);  // Q
    gemm_tf32_kernel<<<gg, 256>>>(image,    Wk, bk, nullptr, 0, 2);  // K
    gemm_tf32_kernel<<<gg, 256>>>(image,    Wv, bv, nullptr, 0, 3);  // V

    // attention (writes result back into g_Q)
    attn_kernel<<<dim3(BATCH, HEADS), 256>>>(bt, ri);

    // output projection from g_Q -> d_out
    gemm_tf32_kernel<<<gg, 256>>>(nullptr, Wo, bo, out, 1, 0);
}